// round 1
// baseline (speedup 1.0000x reference)
#include <cuda_runtime.h>

// Problem constants (fixed shapes from reference setup_inputs)
#define NS      512            // N samples
#define KSEG    16             // segments
#define SEGD    8192           // 1024*128/16 elements per segment
#define FSTRIDE (KSEG * SEGD)  // 131072 floats per sample
#define TEMP_INV (1.0f / 0.7f)

#define NTILE   64
#define NTILES  (NS / NTILE)                 // 8
#define NPAIRS  (NTILES * (NTILES + 1) / 2)  // 36 symmetric tile pairs

// Scratch (device globals: no allocation allowed in kernel_launch)
__device__ float g_sims[KSEG * NS * NS];   // [k][a][b], 16.8 MB
__device__ int   g_labels[NS];
__device__ float g_partials[1024];

// ---------------------------------------------------------------------------
// Labels may arrive as int32 (JAX default) or int64 (x64 enabled). Values are
// 0..9. If int64 (little-endian), every odd 32-bit word of the first 512
// words is the zero high-half. If int32, ~90% of odd words are nonzero
// labels, so "all odd words zero" is a safe dtype discriminator.
// Reads stay within the smaller (int32) buffer size: words 0..511.
// ---------------------------------------------------------------------------
__global__ void prep_labels_kernel(const int* __restrict__ lab) {
    int t = threadIdx.x;  // 512 threads
    int viol = 0;
    if (t < NS / 2) viol = (lab[2 * t + 1] != 0) ? 1 : 0;
    int is_int32 = __syncthreads_or(viol);
    g_labels[t] = is_int32 ? lab[t] : lab[2 * t];
}

// ---------------------------------------------------------------------------
// Segment Gram GEMM: C_k = F_k * F_k^T / TEMP, F_k = [512 x 8192] f32.
// Symmetric: compute only tile pairs (bi <= bj), mirror-store the rest.
// 64x64 tile per block, 256 threads, 4x4 micro-tile per thread, BK=16,
// k-major (transposed) smem so compute reads are LDS.128.
// ---------------------------------------------------------------------------
__global__ __launch_bounds__(256)
void seg_gemm_kernel(const float* __restrict__ F) {
    __shared__ __align__(16) float As[16][68];  // [kk][row], 68 = pad, keeps 16B align
    __shared__ __align__(16) float Bs[16][68];

    const int seg = blockIdx.y;

    // decode symmetric tile pair (bi <= bj)
    int p = blockIdx.x;
    int bi = 0;
    while (p >= NTILES - bi) { p -= NTILES - bi; bi++; }
    const int bj = bi + p;

    const int t    = threadIdx.x;
    const int lrow = t >> 2;          // 0..63 : tile row this thread loads
    const int ld0  = (t & 3) * 4;     // 0,4,8,12 : k-offset of its float4
    const int tx   = t & 15;
    const int ty   = t >> 4;
    const int ra   = ty * 4;          // micro-tile row base (A side)
    const int cb   = tx * 4;          // micro-tile col base (B side)

    const float* Arow = F + (size_t)(bi * NTILE + lrow) * FSTRIDE + seg * SEGD + ld0;
    const float* Brow = F + (size_t)(bj * NTILE + lrow) * FSTRIDE + seg * SEGD + ld0;

    float acc[4][4];
#pragma unroll
    for (int i = 0; i < 4; i++)
#pragma unroll
        for (int j = 0; j < 4; j++) acc[i][j] = 0.0f;

    for (int kt = 0; kt < SEGD; kt += 16) {
        const float4 av = *(const float4*)(Arow + kt);
        const float4 bv = *(const float4*)(Brow + kt);

        __syncthreads();  // previous compute done before overwriting tiles
        As[ld0 + 0][lrow] = av.x;
        As[ld0 + 1][lrow] = av.y;
        As[ld0 + 2][lrow] = av.z;
        As[ld0 + 3][lrow] = av.w;
        Bs[ld0 + 0][lrow] = bv.x;
        Bs[ld0 + 1][lrow] = bv.y;
        Bs[ld0 + 2][lrow] = bv.z;
        Bs[ld0 + 3][lrow] = bv.w;
        __syncthreads();

#pragma unroll
        for (int kk = 0; kk < 16; kk++) {
            const float4 a = *(const float4*)&As[kk][ra];
            const float4 b = *(const float4*)&Bs[kk][cb];
            acc[0][0] += a.x * b.x; acc[0][1] += a.x * b.y;
            acc[0][2] += a.x * b.z; acc[0][3] += a.x * b.w;
            acc[1][0] += a.y * b.x; acc[1][1] += a.y * b.y;
            acc[1][2] += a.y * b.z; acc[1][3] += a.y * b.w;
            acc[2][0] += a.z * b.x; acc[2][1] += a.z * b.y;
            acc[2][2] += a.z * b.z; acc[2][3] += a.z * b.w;
            acc[3][0] += a.w * b.x; acc[3][1] += a.w * b.y;
            acc[3][2] += a.w * b.z; acc[3][3] += a.w * b.w;
        }
    }

    float* C = g_sims + seg * (NS * NS);
    const int garow = bi * NTILE + ra;
    const int gbcol = bj * NTILE + cb;

#pragma unroll
    for (int i = 0; i < 4; i++) {
        float4 v;
        v.x = acc[i][0] * TEMP_INV;
        v.y = acc[i][1] * TEMP_INV;
        v.z = acc[i][2] * TEMP_INV;
        v.w = acc[i][3] * TEMP_INV;
        *(float4*)&C[(garow + i) * NS + gbcol] = v;
    }
    if (bi != bj) {  // mirror store (values identical by symmetry)
#pragma unroll
        for (int i = 0; i < 4; i++)
#pragma unroll
            for (int j = 0; j < 4; j++)
                C[(gbcol + j) * NS + (garow + i)] = acc[i][j] * TEMP_INV;
    }
}

// ---------------------------------------------------------------------------
// Per-pair loss: softmax over 16 segments, ratio of top-4 exp sum to total,
// masked by (labels equal && a != b). Deterministic block tree-reduce to
// g_partials (no float atomics -> bitwise-reproducible output).
// ---------------------------------------------------------------------------
__global__ __launch_bounds__(256)
void reduce_kernel() {
    const int p = blockIdx.x * 256 + threadIdx.x;  // pair id, 0..262143
    const int a = p >> 9;
    const int b = p & (NS - 1);

    float v[KSEG];
    float m = -1e30f;
#pragma unroll
    for (int k = 0; k < KSEG; k++) {
        v[k] = g_sims[k * (NS * NS) + p];
        m = fmaxf(m, v[k]);
    }

    float tot = 0.0f;
    float t0 = 0.0f, t1 = 0.0f, t2 = 0.0f, t3 = 0.0f;  // exp > 0, so 0-init is safe
#pragma unroll
    for (int k = 0; k < KSEG; k++) {
        const float e = __expf(v[k] - m);
        tot += e;
        if (e > t0)      { t3 = t2; t2 = t1; t1 = t0; t0 = e; }
        else if (e > t1) { t3 = t2; t2 = t1; t1 = e; }
        else if (e > t2) { t3 = t2; t2 = e; }
        else if (e > t3) { t3 = e; }
    }

    float loss = 0.0f;
    if (a != b && g_labels[a] == g_labels[b])
        loss = -__logf((t0 + t1 + t2 + t3) / tot);

    __shared__ float red[256];
    red[threadIdx.x] = loss;
    __syncthreads();
#pragma unroll
    for (int s = 128; s > 0; s >>= 1) {
        if (threadIdx.x < s) red[threadIdx.x] += red[threadIdx.x + s];
        __syncthreads();
    }
    if (threadIdx.x == 0) g_partials[blockIdx.x] = red[0];
}

__global__ void finalize_kernel(float* __restrict__ out) {
    __shared__ float red[256];
    const int t = threadIdx.x;
    red[t] = g_partials[t] + g_partials[t + 256] +
             g_partials[t + 512] + g_partials[t + 768];
    __syncthreads();
#pragma unroll
    for (int s = 128; s > 0; s >>= 1) {
        if (t < s) red[t] += red[t + s];
        __syncthreads();
    }
    if (t == 0) out[0] = red[0] / (float)(NS * NS);
}

// ---------------------------------------------------------------------------
extern "C" void kernel_launch(void* const* d_in, const int* in_sizes, int n_in,
                              void* d_out, int out_size) {
    const float* features = (const float*)d_in[0];
    const int*   labels   = (const int*)d_in[1];   // dtype resolved on-device
    // d_in[2] (preds) is unused by the reference output.
    (void)in_sizes; (void)n_in; (void)out_size;

    prep_labels_kernel<<<1, NS>>>(labels);

    dim3 grid(NPAIRS, KSEG);
    seg_gemm_kernel<<<grid, 256>>>(features);

    reduce_kernel<<<(NS * NS) / 256, 256>>>();

    finalize_kernel<<<1, 256>>>((float*)d_out);
}

// round 3
// speedup vs baseline: 4.6317x; 4.6317x over previous
#include <cuda_runtime.h>
#include <cuda_bf16.h>
#include <cstdint>

// ---------------- problem constants ----------------
#define NS      512
#define KSEG    16
#define SEGD    8192
#define FSTRIDE (KSEG * SEGD)
// 1/sqrt(0.7) folded into each bf16 operand -> MMA emits sims/TEMP directly
#define OP_SCALE 1.1952286093343936f

// ---------------- GEMM tiling ----------------
#define MT      128
#define CK      64                    // bf16 K per chunk (128B rows -> SW128)
#define NCHUNK  (SEGD / CK)           // 128
#define STAGES  3
#define OP_BYTES   (MT * 128)         // 16384 per operand per stage
#define STAGE_BYTES (2 * OP_BYTES)    // 32768
#define SMEM_DYN (1024 + STAGES * STAGE_BYTES)  // 99328

#define NTILES  (NS / MT)             // 4
#define NPAIRS  (NTILES * (NTILES + 1) / 2)   // 10

// ---------------- device scratch ----------------
__device__ __align__(16) __nv_bfloat16 g_fb16[(size_t)KSEG * NS * SEGD]; // [k][n][d]
__device__ float g_sims[(size_t)KSEG * NS * NS];                          // [k][a][b]
__device__ int   g_labels[NS];
__device__ float g_partials[1024];

// ---------------- helpers ----------------
__device__ __forceinline__ uint32_t smem_u32(const void* p) {
    uint32_t a;
    asm("{ .reg .u64 t; cvta.to.shared.u64 t, %1; cvt.u32.u64 %0, t; }" : "=r"(a) : "l"(p));
    return a;
}
#define CP16(dst, src) \
    asm volatile("cp.async.cg.shared.global [%0], [%1], 16;" :: "r"(dst), "l"(src))
#define CP_COMMIT() asm volatile("cp.async.commit_group;" ::: "memory")
template <int N> __device__ __forceinline__ void cp_wait() {
    asm volatile("cp.async.wait_group %0;" :: "n"(N) : "memory");
}
#define SW128(o) ((o) ^ (((o) >> 3) & 0x70))

__device__ __forceinline__ void ldsm_x4(uint32_t& r0, uint32_t& r1, uint32_t& r2, uint32_t& r3,
                                        uint32_t addr) {
    asm volatile("ldmatrix.sync.aligned.m8n8.x4.shared.b16 {%0,%1,%2,%3}, [%4];"
                 : "=r"(r0), "=r"(r1), "=r"(r2), "=r"(r3) : "r"(addr));
}
__device__ __forceinline__ void mma16816(float* c, const uint32_t* a, uint32_t b0, uint32_t b1) {
    asm volatile(
        "mma.sync.aligned.m16n8k16.row.col.f32.bf16.bf16.f32 "
        "{%0,%1,%2,%3}, {%4,%5,%6,%7}, {%8,%9}, {%0,%1,%2,%3};"
        : "+f"(c[0]), "+f"(c[1]), "+f"(c[2]), "+f"(c[3])
        : "r"(a[0]), "r"(a[1]), "r"(a[2]), "r"(a[3]), "r"(b0), "r"(b1));
}

// ---------------------------------------------------------------------------
// Labels: int32 (JAX default) vs int64 detection (values 0..9 -> high words 0)
// ---------------------------------------------------------------------------
__global__ void prep_labels_kernel(const int* __restrict__ lab) {
    int t = threadIdx.x;
    int viol = 0;
    if (t < NS / 2) viol = (lab[2 * t + 1] != 0) ? 1 : 0;
    int is_int32 = __syncthreads_or(viol);
    g_labels[t] = is_int32 ? lab[t] : lab[2 * t];
}

// ---------------------------------------------------------------------------
// f32 -> bf16 with scale fold; layout transpose [n][k][d] -> [k][n][d]
// ---------------------------------------------------------------------------
__global__ __launch_bounds__(256) void convert_kernel(const float* __restrict__ F) {
    size_t t = (size_t)blockIdx.x * 256 + threadIdx.x;
    size_t e = t * 8;
    const float4* src = (const float4*)(F + e);
    float4 a = src[0], b = src[1];
    a.x *= OP_SCALE; a.y *= OP_SCALE; a.z *= OP_SCALE; a.w *= OP_SCALE;
    b.x *= OP_SCALE; b.y *= OP_SCALE; b.z *= OP_SCALE; b.w *= OP_SCALE;

    __nv_bfloat162 h0 = __floats2bfloat162_rn(a.x, a.y);
    __nv_bfloat162 h1 = __floats2bfloat162_rn(a.z, a.w);
    __nv_bfloat162 h2 = __floats2bfloat162_rn(b.x, b.y);
    __nv_bfloat162 h3 = __floats2bfloat162_rn(b.z, b.w);

    uint32_t r = (uint32_t)(e >> 13);       // n*16 + k
    uint32_t d = (uint32_t)(e & 8191);
    uint32_t n = r >> 4, k = r & 15;
    __nv_bfloat16* dst = g_fb16 + ((size_t)k * NS + n) * SEGD + d;
    uint4 v;
    v.x = *(uint32_t*)&h0; v.y = *(uint32_t*)&h1;
    v.z = *(uint32_t*)&h2; v.w = *(uint32_t*)&h3;
    *(uint4*)dst = v;
}

// ---------------------------------------------------------------------------
// HMMA segment Gram GEMM: per CTA, C tile [128x128] of F_k F_k^T (pre-scaled).
// Symmetric tile pairs (bi<=bj), mirror store for off-diagonal pairs.
// 8 warps (4x2), warp tile 32(m) x 64(n), mma.m16n8k16 bf16->f32.
// 3-stage cp.async pipeline, SW128-swizzled 128B smem rows, conflict-free LDSM.
// ---------------------------------------------------------------------------
__global__ __launch_bounds__(256, 2) void seg_gemm_kernel() {
    extern __shared__ __align__(1024) char smem_raw[];
    uint32_t sbase = (smem_u32(smem_raw) + 1023) & ~1023u;

    const int tid  = threadIdx.x;
    const int lane = tid & 31;
    const int wid  = tid >> 5;
    const int wm   = wid & 3;           // 4 warps along M (32 rows each)
    const int wn   = wid >> 2;          // 2 warps along N (64 cols each)

    const int seg = blockIdx.y;
    int p = blockIdx.x;                 // symmetric pair id 0..9
    int bi = 0;
    while (p >= NTILES - bi) { p -= NTILES - bi; bi++; }
    const int bj = bi + p;

    const __nv_bfloat16* gA = g_fb16 + ((size_t)seg * NS + bi * MT) * SEGD;
    const __nv_bfloat16* gB = g_fb16 + ((size_t)seg * NS + bj * MT) * SEGD;

    float acc[2][8][4];
#pragma unroll
    for (int i = 0; i < 2; i++)
#pragma unroll
        for (int j = 0; j < 8; j++)
#pragma unroll
            for (int q = 0; q < 4; q++) acc[i][j][q] = 0.0f;

    auto load_chunk = [&](int c) {
        uint32_t st = sbase + (c % STAGES) * STAGE_BYTES;
        int kb = c * CK;
#pragma unroll
        for (int i = 0; i < 8; i++) {
            int q = i * 256 + tid;
            int row = q >> 3, g = q & 7;
            if (row < MT) {
                CP16(st + SW128(row * 128 + g * 16),
                     gA + (size_t)row * SEGD + kb + g * 8);
            } else {
                int r2 = row - MT;
                CP16(st + OP_BYTES + SW128(r2 * 128 + g * 16),
                     gB + (size_t)r2 * SEGD + kb + g * 8);
            }
        }
        CP_COMMIT();
    };

    const int lrow  = lane & 15;
    const int khalf = (lane >> 4) & 1;

    auto compute = [&](int cs) {
        uint32_t sa = sbase + cs * STAGE_BYTES;
        uint32_t sb = sa + OP_BYTES;
#pragma unroll
        for (int ks = 0; ks < 4; ks++) {           // 4 x k16 per chunk
            const int kb = ks * 32 + khalf * 16;   // byte offset in 128B row
            uint32_t a[2][4], bf[4][4];
#pragma unroll
            for (int im = 0; im < 2; im++) {
                int row = wm * 32 + im * 16 + lrow;
                ldsm_x4(a[im][0], a[im][1], a[im][2], a[im][3],
                        sa + SW128(row * 128 + kb));
            }
#pragma unroll
            for (int j2 = 0; j2 < 4; j2++) {       // each covers n16
                int row = wn * 64 + j2 * 16 + lrow;
                ldsm_x4(bf[j2][0], bf[j2][1], bf[j2][2], bf[j2][3],
                        sb + SW128(row * 128 + kb));
            }
#pragma unroll
            for (int im = 0; im < 2; im++)
#pragma unroll
                for (int jn = 0; jn < 8; jn++)
                    mma16816(acc[im][jn], a[im], bf[jn >> 1][jn & 1], bf[jn >> 1][2 + (jn & 1)]);
        }
    };

    load_chunk(0);
    load_chunk(1);
    for (int c = 0; c < NCHUNK; c++) {
        cp_wait<1>();
        __syncthreads();
        compute(c % STAGES);
        if (c + 2 < NCHUNK) load_chunk(c + 2);
        else CP_COMMIT();                 // empty group keeps wait<1> semantics
    }

    // Epilogue: direct + mirrored stores (operand scale fold => values are sims/T)
    float* Cseg = g_sims + (size_t)seg * NS * NS;
    const int gid = lane >> 2, tig = lane & 3;
#pragma unroll
    for (int im = 0; im < 2; im++) {
#pragma unroll
        for (int jn = 0; jn < 8; jn++) {
            int r0 = bi * MT + wm * 32 + im * 16 + gid;
            int c0 = bj * MT + wn * 64 + jn * 8 + tig * 2;
            float2 v01 = make_float2(acc[im][jn][0], acc[im][jn][1]);
            float2 v23 = make_float2(acc[im][jn][2], acc[im][jn][3]);
            *(float2*)&Cseg[(size_t)r0 * NS + c0] = v01;
            *(float2*)&Cseg[(size_t)(r0 + 8) * NS + c0] = v23;
            if (bi != bj) {
                Cseg[(size_t)c0 * NS + r0]           = v01.x;
                Cseg[(size_t)(c0 + 1) * NS + r0]     = v01.y;
                Cseg[(size_t)c0 * NS + r0 + 8]       = v23.x;
                Cseg[(size_t)(c0 + 1) * NS + r0 + 8] = v23.y;
            }
        }
    }
}

// ---------------------------------------------------------------------------
// Per-pair loss: top-4-of-16 exp ratio, masked, deterministic tree reduce.
// ---------------------------------------------------------------------------
__global__ __launch_bounds__(256) void reduce_kernel() {
    const int p = blockIdx.x * 256 + threadIdx.x;
    const int a = p >> 9;
    const int b = p & (NS - 1);

    float v[KSEG];
    float m = -1e30f;
#pragma unroll
    for (int k = 0; k < KSEG; k++) {
        v[k] = g_sims[(size_t)k * (NS * NS) + p];
        m = fmaxf(m, v[k]);
    }
    float tot = 0.0f, t0 = 0.0f, t1 = 0.0f, t2 = 0.0f, t3 = 0.0f;
#pragma unroll
    for (int k = 0; k < KSEG; k++) {
        const float e = __expf(v[k] - m);
        tot += e;
        if (e > t0)      { t3 = t2; t2 = t1; t1 = t0; t0 = e; }
        else if (e > t1) { t3 = t2; t2 = t1; t1 = e; }
        else if (e > t2) { t3 = t2; t2 = e; }
        else if (e > t3) { t3 = e; }
    }
    float loss = 0.0f;
    if (a != b && g_labels[a] == g_labels[b])
        loss = -__logf((t0 + t1 + t2 + t3) / tot);

    __shared__ float red[256];
    red[threadIdx.x] = loss;
    __syncthreads();
#pragma unroll
    for (int s = 128; s > 0; s >>= 1) {
        if (threadIdx.x < s) red[threadIdx.x] += red[threadIdx.x + s];
        __syncthreads();
    }
    if (threadIdx.x == 0) g_partials[blockIdx.x] = red[0];
}

__global__ void finalize_kernel(float* __restrict__ out) {
    __shared__ float red[256];
    const int t = threadIdx.x;
    red[t] = g_partials[t] + g_partials[t + 256] + g_partials[t + 512] + g_partials[t + 768];
    __syncthreads();
#pragma unroll
    for (int s = 128; s > 0; s >>= 1) {
        if (t < s) red[t] += red[t + s];
        __syncthreads();
    }
    if (t == 0) out[0] = red[0] / (float)(NS * NS);
}

// ---------------------------------------------------------------------------
extern "C" void kernel_launch(void* const* d_in, const int* in_sizes, int n_in,
                              void* d_out, int out_size) {
    const float* features = (const float*)d_in[0];
    const int*   labels   = (const int*)d_in[1];
    (void)in_sizes; (void)n_in; (void)out_size;

    cudaFuncSetAttribute(seg_gemm_kernel, cudaFuncAttributeMaxDynamicSharedMemorySize, SMEM_DYN);

    prep_labels_kernel<<<1, NS>>>(labels);
    convert_kernel<<<(NS * FSTRIDE) / (256 * 8), 256>>>(features);

    dim3 grid(NPAIRS, KSEG);  // 10 symmetric pairs x 16 segments = 160 CTAs
    seg_gemm_kernel<<<grid, 256, SMEM_DYN>>>();

    reduce_kernel<<<(NS * NS) / 256, 256>>>();
    finalize_kernel<<<1, 256>>>((float*)d_out);
}

// round 4
// speedup vs baseline: 5.5079x; 1.1892x over previous
#include <cuda_runtime.h>
#include <cuda_bf16.h>
#include <cstdint>

// ---------------- problem constants ----------------
#define NS      512
#define KSEG    16
#define SEGD    8192
#define FSTRIDE (KSEG * SEGD)
// 1/sqrt(0.7) folded into each bf16 operand -> MMA emits sims/TEMP directly
#define OP_SCALE 1.1952286093343936f

// ---------------- GEMM tiling ----------------
#define MT      128
#define CK      64                    // bf16 K per chunk (128B rows -> SW128)
#define KHALF   (SEGD / 2)            // 4096 per K-split half
#define NCHUNKH (KHALF / CK)          // 64 chunks per half
#define STAGES  3
#define OP_BYTES   (MT * 128)         // 16384 per operand per stage
#define STAGE_BYTES (2 * OP_BYTES)    // 32768
#define SMEM_DYN (1024 + STAGES * STAGE_BYTES)  // 99328 -> 2 CTAs/SM

#define NTILES  (NS / MT)             // 4
#define NPAIRS  (NTILES * (NTILES + 1) / 2)   // 10

// ---------------- device scratch ----------------
__device__ __align__(16) __nv_bfloat16 g_fb16[(size_t)KSEG * NS * SEGD]; // [k][n][d]
__device__ float g_sims [(size_t)KSEG * NS * NS];   // K-half 0
__device__ float g_sims2[(size_t)KSEG * NS * NS];   // K-half 1
__device__ float g_partials[1024];
__device__ int   g_red_count;                        // self-resetting

// ---------------- helpers ----------------
__device__ __forceinline__ uint32_t smem_u32(const void* p) {
    uint32_t a;
    asm("{ .reg .u64 t; cvta.to.shared.u64 t, %1; cvt.u32.u64 %0, t; }" : "=r"(a) : "l"(p));
    return a;
}
#define CP16(dst, src) \
    asm volatile("cp.async.cg.shared.global [%0], [%1], 16;" :: "r"(dst), "l"(src))
#define CP_COMMIT() asm volatile("cp.async.commit_group;" ::: "memory")
template <int N> __device__ __forceinline__ void cp_wait() {
    asm volatile("cp.async.wait_group %0;" :: "n"(N) : "memory");
}
#define SW128(o) ((o) ^ (((o) >> 3) & 0x70))

__device__ __forceinline__ void ldsm_x4(uint32_t& r0, uint32_t& r1, uint32_t& r2, uint32_t& r3,
                                        uint32_t addr) {
    asm volatile("ldmatrix.sync.aligned.m8n8.x4.shared.b16 {%0,%1,%2,%3}, [%4];"
                 : "=r"(r0), "=r"(r1), "=r"(r2), "=r"(r3) : "r"(addr));
}
__device__ __forceinline__ void mma16816(float* c, const uint32_t* a, uint32_t b0, uint32_t b1) {
    asm volatile(
        "mma.sync.aligned.m16n8k16.row.col.f32.bf16.bf16.f32 "
        "{%0,%1,%2,%3}, {%4,%5,%6,%7}, {%8,%9}, {%0,%1,%2,%3};"
        : "+f"(c[0]), "+f"(c[1]), "+f"(c[2]), "+f"(c[3])
        : "r"(a[0]), "r"(a[1]), "r"(a[2]), "r"(a[3]), "r"(b0), "r"(b1));
}

// ---------------------------------------------------------------------------
// f32 -> bf16 with scale fold; layout transpose [n][k][d] -> [k][n][d]
// ---------------------------------------------------------------------------
__global__ __launch_bounds__(256) void convert_kernel(const float* __restrict__ F) {
    size_t t = (size_t)blockIdx.x * 256 + threadIdx.x;
    size_t e = t * 8;
    const float4* src = (const float4*)(F + e);
    float4 a = src[0], b = src[1];
    a.x *= OP_SCALE; a.y *= OP_SCALE; a.z *= OP_SCALE; a.w *= OP_SCALE;
    b.x *= OP_SCALE; b.y *= OP_SCALE; b.z *= OP_SCALE; b.w *= OP_SCALE;

    __nv_bfloat162 h0 = __floats2bfloat162_rn(a.x, a.y);
    __nv_bfloat162 h1 = __floats2bfloat162_rn(a.z, a.w);
    __nv_bfloat162 h2 = __floats2bfloat162_rn(b.x, b.y);
    __nv_bfloat162 h3 = __floats2bfloat162_rn(b.z, b.w);

    uint32_t r = (uint32_t)(e >> 13);       // n*16 + k
    uint32_t d = (uint32_t)(e & 8191);
    uint32_t n = r >> 4, k = r & 15;
    __nv_bfloat16* dst = g_fb16 + ((size_t)k * NS + n) * SEGD + d;
    uint4 v;
    v.x = *(uint32_t*)&h0; v.y = *(uint32_t*)&h1;
    v.z = *(uint32_t*)&h2; v.w = *(uint32_t*)&h3;
    *(uint4*)dst = v;
}

// ---------------------------------------------------------------------------
// HMMA segment Gram GEMM, K-split 2 for load balance:
// grid (10 symmetric pairs, 16 segments, 2 K-halves) = 320 CTAs.
// Per CTA: C_half[128x128] = A[128x4096] B[128x4096]^T into g_sims / g_sims2.
// 8 warps (4x2), warp tile 32(m) x 64(n), mma.m16n8k16 bf16->f32,
// 3-stage cp.async pipeline, SW128 swizzle, conflict-free LDSM.
// ---------------------------------------------------------------------------
__global__ __launch_bounds__(256, 2) void seg_gemm_kernel() {
    extern __shared__ __align__(1024) char smem_raw[];
    uint32_t sbase = (smem_u32(smem_raw) + 1023) & ~1023u;

    const int tid  = threadIdx.x;
    const int lane = tid & 31;
    const int wid  = tid >> 5;
    const int wm   = wid & 3;
    const int wn   = wid >> 2;

    const int seg  = blockIdx.y;
    const int kh   = blockIdx.z;        // K-split half
    int p = blockIdx.x;
    int bi = 0;
    while (p >= NTILES - bi) { p -= NTILES - bi; bi++; }
    const int bj = bi + p;

    const __nv_bfloat16* gA = g_fb16 + ((size_t)seg * NS + bi * MT) * SEGD + kh * KHALF;
    const __nv_bfloat16* gB = g_fb16 + ((size_t)seg * NS + bj * MT) * SEGD + kh * KHALF;

    float acc[2][8][4];
#pragma unroll
    for (int i = 0; i < 2; i++)
#pragma unroll
        for (int j = 0; j < 8; j++)
#pragma unroll
            for (int q = 0; q < 4; q++) acc[i][j][q] = 0.0f;

    auto load_chunk = [&](int c) {
        uint32_t st = sbase + (c % STAGES) * STAGE_BYTES;
        int kb = c * CK;
#pragma unroll
        for (int i = 0; i < 8; i++) {
            int q = i * 256 + tid;
            int row = q >> 3, g = q & 7;
            if (row < MT) {
                CP16(st + SW128(row * 128 + g * 16),
                     gA + (size_t)row * SEGD + kb + g * 8);
            } else {
                int r2 = row - MT;
                CP16(st + OP_BYTES + SW128(r2 * 128 + g * 16),
                     gB + (size_t)r2 * SEGD + kb + g * 8);
            }
        }
        CP_COMMIT();
    };

    const int lrow  = lane & 15;
    const int khf   = (lane >> 4) & 1;

    auto compute = [&](int cs) {
        uint32_t sa = sbase + cs * STAGE_BYTES;
        uint32_t sb = sa + OP_BYTES;
#pragma unroll
        for (int ks = 0; ks < 4; ks++) {
            const int kb = ks * 32 + khf * 16;
            uint32_t a[2][4], bf[4][4];
#pragma unroll
            for (int im = 0; im < 2; im++) {
                int row = wm * 32 + im * 16 + lrow;
                ldsm_x4(a[im][0], a[im][1], a[im][2], a[im][3],
                        sa + SW128(row * 128 + kb));
            }
#pragma unroll
            for (int j2 = 0; j2 < 4; j2++) {
                int row = wn * 64 + j2 * 16 + lrow;
                ldsm_x4(bf[j2][0], bf[j2][1], bf[j2][2], bf[j2][3],
                        sb + SW128(row * 128 + kb));
            }
#pragma unroll
            for (int im = 0; im < 2; im++)
#pragma unroll
                for (int jn = 0; jn < 8; jn++)
                    mma16816(acc[im][jn], a[im], bf[jn >> 1][jn & 1], bf[jn >> 1][2 + (jn & 1)]);
        }
    };

    load_chunk(0);
    load_chunk(1);
    for (int c = 0; c < NCHUNKH; c++) {
        cp_wait<1>();
        __syncthreads();
        compute(c % STAGES);
        if (c + 2 < NCHUNKH) load_chunk(c + 2);
        else CP_COMMIT();
    }

    float* Cseg = (kh ? g_sims2 : g_sims) + (size_t)seg * NS * NS;
    const int gid = lane >> 2, tig = lane & 3;
#pragma unroll
    for (int im = 0; im < 2; im++) {
#pragma unroll
        for (int jn = 0; jn < 8; jn++) {
            int r0 = bi * MT + wm * 32 + im * 16 + gid;
            int c0 = bj * MT + wn * 64 + jn * 8 + tig * 2;
            float2 v01 = make_float2(acc[im][jn][0], acc[im][jn][1]);
            float2 v23 = make_float2(acc[im][jn][2], acc[im][jn][3]);
            *(float2*)&Cseg[(size_t)r0 * NS + c0] = v01;
            *(float2*)&Cseg[(size_t)(r0 + 8) * NS + c0] = v23;
            if (bi != bj) {
                Cseg[(size_t)c0 * NS + r0]           = v01.x;
                Cseg[(size_t)(c0 + 1) * NS + r0]     = v01.y;
                Cseg[(size_t)c0 * NS + r0 + 8]       = v23.x;
                Cseg[(size_t)(c0 + 1) * NS + r0 + 8] = v23.y;
            }
        }
    }
}

// ---------------------------------------------------------------------------
// Per-pair loss with fused label handling and fused final reduction.
// Labels: int32 (JAX default) vs int64 detect (values 0..9 -> odd words zero).
// Deterministic: fixed-shape tree reduce; last block (atomic counter,
// self-resetting) folds the 1024 partials and writes the mean.
// ---------------------------------------------------------------------------
__global__ __launch_bounds__(256) void reduce_kernel(const int* __restrict__ lab,
                                                     float* __restrict__ out) {
    const int t = threadIdx.x;
    // dtype detect: words 1,3,...,511 all zero <=> int64
    int viol = (lab[2 * t + 1] != 0) ? 1 : 0;
    int is_int32 = __syncthreads_or(viol);

    const int p = blockIdx.x * 256 + t;
    const int a = p >> 9;
    const int b = p & (NS - 1);

    float v[KSEG];
    float m = -1e30f;
#pragma unroll
    for (int k = 0; k < KSEG; k++) {
        v[k] = g_sims[(size_t)k * (NS * NS) + p] + g_sims2[(size_t)k * (NS * NS) + p];
        m = fmaxf(m, v[k]);
    }
    float tot = 0.0f, t0 = 0.0f, t1 = 0.0f, t2 = 0.0f, t3 = 0.0f;
#pragma unroll
    for (int k = 0; k < KSEG; k++) {
        const float e = __expf(v[k] - m);
        tot += e;
        if (e > t0)      { t3 = t2; t2 = t1; t1 = t0; t0 = e; }
        else if (e > t1) { t3 = t2; t2 = t1; t1 = e; }
        else if (e > t2) { t3 = t2; t2 = e; }
        else if (e > t3) { t3 = e; }
    }
    const int la = is_int32 ? lab[a] : lab[2 * a];
    const int lb = is_int32 ? lab[b] : lab[2 * b];
    float loss = 0.0f;
    if (a != b && la == lb)
        loss = -__logf((t0 + t1 + t2 + t3) / tot);

    __shared__ float red[256];
    red[t] = loss;
    __syncthreads();
#pragma unroll
    for (int s = 128; s > 0; s >>= 1) {
        if (t < s) red[t] += red[t + s];
        __syncthreads();
    }

    __shared__ int isLast;
    if (t == 0) {
        g_partials[blockIdx.x] = red[0];
        __threadfence();
        int c = atomicAdd(&g_red_count, 1);
        isLast = (c == gridDim.x - 1);
    }
    __syncthreads();

    if (isLast) {
        float s = __ldcg(&g_partials[t])       + __ldcg(&g_partials[t + 256])
                + __ldcg(&g_partials[t + 512]) + __ldcg(&g_partials[t + 768]);
        red[t] = s;
        __syncthreads();
#pragma unroll
        for (int sh = 128; sh > 0; sh >>= 1) {
            if (t < sh) red[t] += red[t + sh];
            __syncthreads();
        }
        if (t == 0) {
            out[0] = red[0] / (float)(NS * NS);
            g_red_count = 0;   // self-reset: deterministic across graph replays
        }
    }
}

// ---------------------------------------------------------------------------
extern "C" void kernel_launch(void* const* d_in, const int* in_sizes, int n_in,
                              void* d_out, int out_size) {
    const float* features = (const float*)d_in[0];
    const int*   labels   = (const int*)d_in[1];
    (void)in_sizes; (void)n_in; (void)out_size;

    cudaFuncSetAttribute(seg_gemm_kernel, cudaFuncAttributeMaxDynamicSharedMemorySize, SMEM_DYN);

    convert_kernel<<<(NS * FSTRIDE) / (256 * 8), 256>>>(features);

    dim3 grid(NPAIRS, KSEG, 2);   // 10 pairs x 16 segs x 2 K-halves = 320 CTAs
    seg_gemm_kernel<<<grid, 256, SMEM_DYN>>>();

    reduce_kernel<<<(NS * NS) / 256, 256>>>(labels, (float*)d_out);
}

// round 5
// speedup vs baseline: 5.7854x; 1.0504x over previous
#include <cuda_runtime.h>
#include <cuda_bf16.h>
#include <cstdint>

// ---------------- problem constants ----------------
#define NS      512
#define KSEG    16
#define SEGD    8192
#define FSTRIDE (KSEG * SEGD)
#define OP_SCALE 1.1952286093343936f   // 1/sqrt(0.7) folded per operand

// ---------------- fused kernel config ----------------
#define NSM     152                    // GB300 SM count; 1 CTA/SM
#define MT      128
#define CK      64                     // bf16 per chunk (128B rows, SW128)
#define KQ      2048                   // K per unit (quarter)
#define CHPU    (KQ / CK)              // 32 chunks per unit
#define STAGES  4
#define OP_BYTES    (MT * 128)         // 16384
#define STAGE_BYTES (2 * OP_BYTES)     // 32768
#define SMEM_DYN (1024 + STAGES * STAGE_BYTES)  // 132096 -> 1 CTA/SM

#define NTILES  4
#define NPAIRS  10
#define NTILE_TOT (NPAIRS * KSEG)      // 160 tiles
#define UNITS   (NTILE_TOT * 4)        // 640

// ---------------- device scratch ----------------
__device__ __align__(16) __nv_bfloat16 g_fb16[(size_t)KSEG * NS * SEGD]; // [k][n][d]
__device__ float g_simsP[(size_t)4 * KSEG * NS * NS];  // [kq][seg][a][b] partials
__device__ float g_partials[1024];
__device__ int   g_red_count;
__device__ int   g_segcnt[KSEG];
__device__ int   g_segflag[KSEG];

// ---------------- helpers ----------------
__device__ __forceinline__ uint32_t smem_u32(const void* p) {
    uint32_t a;
    asm("{ .reg .u64 t; cvta.to.shared.u64 t, %1; cvt.u32.u64 %0, t; }" : "=r"(a) : "l"(p));
    return a;
}
#define CP16(dst, src) \
    asm volatile("cp.async.cg.shared.global [%0], [%1], 16;" :: "r"(dst), "l"(src))
#define CP_COMMIT() asm volatile("cp.async.commit_group;" ::: "memory")
template <int N> __device__ __forceinline__ void cp_wait() {
    asm volatile("cp.async.wait_group %0;" :: "n"(N) : "memory");
}
#define SW128(o) ((o) ^ (((o) >> 3) & 0x70))
#define BAR_MMA()  asm volatile("bar.sync 1, 256;" ::: "memory")
#define BAR_CONV() asm volatile("bar.sync 2, 128;" ::: "memory")

__device__ __forceinline__ void ldsm_x4(uint32_t& r0, uint32_t& r1, uint32_t& r2, uint32_t& r3,
                                        uint32_t addr) {
    asm volatile("ldmatrix.sync.aligned.m8n8.x4.shared.b16 {%0,%1,%2,%3}, [%4];"
                 : "=r"(r0), "=r"(r1), "=r"(r2), "=r"(r3) : "r"(addr));
}
__device__ __forceinline__ void mma16816(float* c, const uint32_t* a, uint32_t b0, uint32_t b1) {
    asm volatile(
        "mma.sync.aligned.m16n8k16.row.col.f32.bf16.bf16.f32 "
        "{%0,%1,%2,%3}, {%4,%5,%6,%7}, {%8,%9}, {%0,%1,%2,%3};"
        : "+f"(c[0]), "+f"(c[1]), "+f"(c[2]), "+f"(c[3])
        : "r"(a[0]), "r"(a[1]), "r"(a[2]), "r"(a[3]), "r"(b0), "r"(b1));
}

// ---------------------------------------------------------------------------
// Fused convert + GEMM. 152 CTAs (1/SM), 384 threads.
//   warps 0-7  : HMMA GEMM consumer (256 threads, named barrier 1)
//   warps 8-11 : f32->bf16 producer, seg-by-seg, per-seg release flags
// Units (tile x K-quarter) dealt u = cta + 152*j so every CTA walks segments
// in lockstep with the producer schedule. Partial sums -> g_simsP[kq].
// ---------------------------------------------------------------------------
__global__ void __launch_bounds__(384)
fused_kernel(const float* __restrict__ F) {
    extern __shared__ __align__(1024) char smem_raw[];
    const int tid = threadIdx.x;
    const int cta = blockIdx.x;

    if (tid >= 256) {
        // ---------------- producer: convert warps ----------------
        const int tc = tid - 256;                   // 0..127
        const uint32_t UPS = (NS * SEGD) / 8;       // 524288 8-elem units per seg
        const uint32_t lo = (uint32_t)(((uint64_t)cta * UPS) / NSM);
        const uint32_t hi = (uint32_t)(((uint64_t)(cta + 1) * UPS) / NSM);
        for (int s = 0; s < KSEG; s++) {
#pragma unroll 4
            for (uint32_t i = lo + tc; i < hi; i += 128) {
                uint32_t e = i * 8;
                uint32_t n = e >> 13, d = e & 8191;
                const float4* src = (const float4*)(F + (size_t)n * FSTRIDE + s * SEGD + d);
                float4 a = src[0], b = src[1];
                a.x *= OP_SCALE; a.y *= OP_SCALE; a.z *= OP_SCALE; a.w *= OP_SCALE;
                b.x *= OP_SCALE; b.y *= OP_SCALE; b.z *= OP_SCALE; b.w *= OP_SCALE;
                __nv_bfloat162 h0 = __floats2bfloat162_rn(a.x, a.y);
                __nv_bfloat162 h1 = __floats2bfloat162_rn(a.z, a.w);
                __nv_bfloat162 h2 = __floats2bfloat162_rn(b.x, b.y);
                __nv_bfloat162 h3 = __floats2bfloat162_rn(b.z, b.w);
                uint4 v;
                v.x = *(uint32_t*)&h0; v.y = *(uint32_t*)&h1;
                v.z = *(uint32_t*)&h2; v.w = *(uint32_t*)&h3;
                *(uint4*)(g_fb16 + ((size_t)s * NS + n) * SEGD + d) = v;
            }
            BAR_CONV();                             // CTA's slice of seg s stored
            if (tc == 0) {
                __threadfence();
                if (atomicAdd(&g_segcnt[s], 1) == NSM - 1) {
                    __threadfence();
                    atomicExch(&g_segflag[s], 1);   // release seg s
                }
            }
        }
        return;
    }

    // ---------------- consumer: GEMM warps ----------------
    uint32_t sbase = (smem_u32(smem_raw) + 1023) & ~1023u;
    const int lane = tid & 31;
    const int wid  = tid >> 5;
    const int wm   = wid & 3;
    const int wn   = wid >> 2;
    const int lrow = lane & 15;
    const int khf  = (lane >> 4) & 1;
    const int gid  = lane >> 2, tig = lane & 3;

    int lastSeg = -1;

    for (int j = 0; j < 5; ++j) {
        int u;
        if (j < 4) u = cta + NSM * j;
        else { if (cta >= UNITS - 4 * NSM) break; u = 4 * NSM + cta; }

        const int tile = u >> 2, kq = u & 3;
        const int seg  = tile / NPAIRS;
        int p = tile % NPAIRS;
        int bi = 0;
        while (p >= NTILES - bi) { p -= NTILES - bi; bi++; }
        const int bj = bi + p;

        if (seg != lastSeg) {                       // acquire-wait for producer
            if (tid == 0) {
                while (atomicAdd(&g_segflag[seg], 0) == 0) __nanosleep(200);
            }
            BAR_MMA();
            lastSeg = seg;
        }

        const __nv_bfloat16* gA = g_fb16 + ((size_t)seg * NS + bi * MT) * SEGD + kq * KQ;
        const __nv_bfloat16* gB = g_fb16 + ((size_t)seg * NS + bj * MT) * SEGD + kq * KQ;

        float acc[2][8][4];
#pragma unroll
        for (int i = 0; i < 2; i++)
#pragma unroll
            for (int jj = 0; jj < 8; jj++)
#pragma unroll
                for (int q = 0; q < 4; q++) acc[i][jj][q] = 0.0f;

        auto load_chunk = [&](int c) {
            uint32_t st = sbase + (c & (STAGES - 1)) * STAGE_BYTES;
            int kb = c * CK;
#pragma unroll
            for (int i = 0; i < 8; i++) {
                int q = i * 256 + tid;
                int row = q >> 3, g = q & 7;
                if (row < MT) {
                    CP16(st + SW128(row * 128 + g * 16),
                         gA + (size_t)row * SEGD + kb + g * 8);
                } else {
                    int r2 = row - MT;
                    CP16(st + OP_BYTES + SW128(r2 * 128 + g * 16),
                         gB + (size_t)r2 * SEGD + kb + g * 8);
                }
            }
            CP_COMMIT();
        };

        auto compute = [&](int cs) {
            uint32_t sa = sbase + cs * STAGE_BYTES;
            uint32_t sb = sa + OP_BYTES;
#pragma unroll
            for (int ks = 0; ks < 4; ks++) {
                const int kb = ks * 32 + khf * 16;
                uint32_t a[2][4], bf[4][4];
#pragma unroll
                for (int im = 0; im < 2; im++) {
                    int row = wm * 32 + im * 16 + lrow;
                    ldsm_x4(a[im][0], a[im][1], a[im][2], a[im][3],
                            sa + SW128(row * 128 + kb));
                }
#pragma unroll
                for (int j2 = 0; j2 < 4; j2++) {
                    int row = wn * 64 + j2 * 16 + lrow;
                    ldsm_x4(bf[j2][0], bf[j2][1], bf[j2][2], bf[j2][3],
                            sb + SW128(row * 128 + kb));
                }
#pragma unroll
                for (int im = 0; im < 2; im++)
#pragma unroll
                    for (int jn = 0; jn < 8; jn++)
                        mma16816(acc[im][jn], a[im],
                                 bf[jn >> 1][jn & 1], bf[jn >> 1][2 + (jn & 1)]);
            }
        };

        load_chunk(0); load_chunk(1); load_chunk(2);
        for (int c = 0; c < CHPU; c++) {
            cp_wait<2>();
            BAR_MMA();
            compute(c & (STAGES - 1));
            if (c + 3 < CHPU) load_chunk(c + 3);
            else CP_COMMIT();
        }

        // partial-tile store (upper tiles only; no mirror)
        float* Cb = g_simsP + (((size_t)kq * KSEG + seg) << 18);
#pragma unroll
        for (int im = 0; im < 2; im++) {
#pragma unroll
            for (int jn = 0; jn < 8; jn++) {
                int r0 = bi * MT + wm * 32 + im * 16 + gid;
                int c0 = bj * MT + wn * 64 + jn * 8 + tig * 2;
                *(float2*)&Cb[(size_t)r0 * NS + c0] =
                    make_float2(acc[im][jn][0], acc[im][jn][1]);
                *(float2*)&Cb[(size_t)(r0 + 8) * NS + c0] =
                    make_float2(acc[im][jn][2], acc[im][jn][3]);
            }
        }
    }
}

// ---------------------------------------------------------------------------
// Loss over upper tile-pairs only (loss(a,b)=loss(b,a); off-diag weight 2).
// Sums 4 K-partials, top-4-of-16 exp ratio, masked; deterministic reduce.
// Last block emits the mean and resets flags/counters for graph replay.
// ---------------------------------------------------------------------------
__global__ __launch_bounds__(256) void reduce_kernel(const int* __restrict__ lab,
                                                     float* __restrict__ out) {
    const int t = threadIdx.x;
    // dtype detect: odd words 1..511 all zero <=> int64 (labels 0..9)
    int viol = (lab[2 * t + 1] != 0) ? 1 : 0;
    int is_int32 = __syncthreads_or(viol);

    const int tp    = blockIdx.x >> 6;            // tile pair 0..9
    const int local = ((blockIdx.x & 63) << 8) + t;
    int pp = tp;
    int bi = 0;
    while (pp >= NTILES - bi) { pp -= NTILES - bi; bi++; }
    const int bj = bi + pp;

    const int a = bi * MT + (local >> 7);
    const int b = bj * MT + (local & 127);
    const size_t idx = (size_t)a * NS + b;

    float v[KSEG];
    float m = -1e30f;
#pragma unroll
    for (int k = 0; k < KSEG; k++) {
        float s = 0.0f;
#pragma unroll
        for (int q = 0; q < 4; q++)
            s += g_simsP[(((size_t)q * KSEG + k) << 18) + idx];
        v[k] = s;
        m = fmaxf(m, s);
    }
    float tot = 0.0f, t0 = 0.0f, t1 = 0.0f, t2 = 0.0f, t3 = 0.0f;
#pragma unroll
    for (int k = 0; k < KSEG; k++) {
        const float e = __expf(v[k] - m);
        tot += e;
        if (e > t0)      { t3 = t2; t2 = t1; t1 = t0; t0 = e; }
        else if (e > t1) { t3 = t2; t2 = t1; t1 = e; }
        else if (e > t2) { t3 = t2; t2 = e; }
        else if (e > t3) { t3 = e; }
    }
    const int la = is_int32 ? lab[a] : lab[2 * a];
    const int lb = is_int32 ? lab[b] : lab[2 * b];
    float loss = 0.0f;
    if (a != b && la == lb) {
        const float w = (bi == bj) ? 1.0f : 2.0f;
        loss = -w * __logf((t0 + t1 + t2 + t3) / tot);
    }

    __shared__ float red[256];
    red[t] = loss;
    __syncthreads();
#pragma unroll
    for (int s = 128; s > 0; s >>= 1) {
        if (t < s) red[t] += red[t + s];
        __syncthreads();
    }

    __shared__ int isLast;
    if (t == 0) {
        g_partials[blockIdx.x] = red[0];
        __threadfence();
        int c = atomicAdd(&g_red_count, 1);
        isLast = (c == gridDim.x - 1);
    }
    __syncthreads();

    if (isLast) {
        float s = __ldcg(&g_partials[t]) + __ldcg(&g_partials[t + 256]);
        if (t + 512 < 640) s += __ldcg(&g_partials[t + 512]);
        red[t] = s;
        __syncthreads();
#pragma unroll
        for (int sh = 128; sh > 0; sh >>= 1) {
            if (t < sh) red[t] += red[t + sh];
            __syncthreads();
        }
        if (t == 0) {
            out[0] = red[0] / (float)(NS * NS);
            g_red_count = 0;                       // reset for next graph replay
#pragma unroll
            for (int k = 0; k < KSEG; k++) { g_segcnt[k] = 0; g_segflag[k] = 0; }
        }
    }
}

// ---------------------------------------------------------------------------
extern "C" void kernel_launch(void* const* d_in, const int* in_sizes, int n_in,
                              void* d_out, int out_size) {
    const float* features = (const float*)d_in[0];
    const int*   labels   = (const int*)d_in[1];
    (void)in_sizes; (void)n_in; (void)out_size;

    cudaFuncSetAttribute(fused_kernel, cudaFuncAttributeMaxDynamicSharedMemorySize, SMEM_DYN);

    fused_kernel<<<NSM, 384, SMEM_DYN>>>(features);
    reduce_kernel<<<NPAIRS * 64, 256>>>(labels, (float*)d_out);
}